// round 5
// baseline (speedup 1.0000x reference)
#include <cuda_runtime.h>
#include <math.h>

// ---------------------------------------------------------------------------
// HoloKVAttention: fused QKV(+LoRA) proj -> RoPE+Hadamard phase -> holographic
// KV compression attention -> O proj(+LoRA).  All fp32.
//
// Shapes: B=2, S=2048, HIDDEN=1024, NUM_HEADS=16, HEAD_DIM=64, K_FACTOR=4,
//         LORA_R=64, ns = S/kf = 512.
// ---------------------------------------------------------------------------

#define HID   1024
#define NH    16
#define HD    64
#define KF    4
#define LR    64
#define BATCH 2
#define SEQ   2048
#define NTOK  (BATCH*SEQ)   // 4096
#define NS    (SEQ/KF)      // 512
#define NBH   (BATCH*NH)    // 32

// ------------------------- device scratch (static) -------------------------
__device__ float g_Q[NTOK*HID];
__device__ float g_K[NTOK*HID];
__device__ float g_V[NTOK*HID];
__device__ float g_XAq[NTOK*LR];
__device__ float g_XAv[NTOK*LR];
__device__ float g_XAo[NTOK*LR];
__device__ float g_Qa[NBH*SEQ*HD];     // rope'd, phase * inv_sqrt_d folded, head-major
__device__ float g_Ks[NBH*SEQ*HD];     // rope'd, phase * 0.5 folded
__device__ float g_Vs[NBH*SEQ*HD];     // phase * 0.5 folded
__device__ float g_fullKT[NBH*HD*NS];  // per (bh): [d][slot]  (transposed for GEMM)
__device__ float g_fullV[NBH*NS*HD];   // per (bh): [slot][d]
__device__ float g_scores[(size_t)NBH*SEQ*NS];  // scores -> softmax weights
__device__ float g_wcurr[NBH*SEQ];
__device__ float g_Ohead[NBH*SEQ*HD];
__device__ float g_Otok[NTOK*HID];
__device__ float2 g_cs_tab[SEQ*32];    // rope cos/sin table

// Hadamard CDMA sign: CDMA[step][dim] = H[step][dim%4]
// negative-bit table packed per (step,col): nibble per step: 0x0,0xA,0xC,0x6
__device__ __forceinline__ float hsign(int step, int col) {
    return ((0x6CA0 >> ((step << 2) | (col & 3))) & 1) ? -1.0f : 1.0f;
}

// ------------------------------ generic SGEMM ------------------------------
// C[M,N] = A[M,K] @ B[K,N]  (+ A2[M,K2] @ B2[K2,N] if A2 != nullptr)
// Optionally batched over blockIdx.z with the given element strides.
// causal: 0 = none
//         1 = scores mode: skip block entirely if n0 > (m0+BM-1)/4   (slot mask)
//         2 = PV mode: limit K loop to ((m0+BM-1)/4)+1 rounded up to BK
template<int BM, int BN, int BK, int TM, int TN>
__global__ __launch_bounds__((BM/TM)*(BN/TN))
void sgemm(const float* __restrict__ A, const float* __restrict__ B,
           float* __restrict__ C,
           int M, int N, int K,
           long long sAb, long long sBb, long long sCb,
           const float* __restrict__ A2, const float* __restrict__ B2, int K2,
           int causal)
{
    constexpr int NT = (BM/TM)*(BN/TN);
    __shared__ float As[BK][BM + 4];
    __shared__ float Bs[BK][BN];

    const int m0 = blockIdx.y * BM;
    const int n0 = blockIdx.x * BN;
    if (causal == 1 && n0 > ((m0 + BM - 1) >> 2)) return;
    int kend = K;
    if (causal == 2) {
        int kl = ((m0 + BM - 1) >> 2) + 1;
        kl = (kl + BK - 1) / BK * BK;
        if (kl < kend) kend = kl;
    }
    const long long batch = blockIdx.z;
    A += batch * sAb; B += batch * sBb; C += batch * sCb;

    const int tid = threadIdx.x;
    const int tx = tid % (BN/TN);
    const int ty = tid / (BN/TN);

    float acc[TM][TN];
    #pragma unroll
    for (int i = 0; i < TM; i++)
        #pragma unroll
        for (int j = 0; j < TN; j++) acc[i][j] = 0.0f;

    float ar[TM], br[TN];

    for (int k0 = 0; k0 < kend; k0 += BK) {
        #pragma unroll
        for (int i = tid; i < BM*BK; i += NT) {
            int r = i / BK, c = i % BK;
            As[c][r] = A[(long long)(m0 + r) * K + (k0 + c)];
        }
        #pragma unroll
        for (int i = tid; i < BK*BN; i += NT) {
            int r = i / BN, c = i % BN;
            Bs[r][c] = B[(long long)(k0 + r) * N + (n0 + c)];
        }
        __syncthreads();
        #pragma unroll
        for (int kk = 0; kk < BK; kk++) {
            #pragma unroll
            for (int i = 0; i < TM; i++) ar[i] = As[kk][ty*TM + i];
            #pragma unroll
            for (int j = 0; j < TN; j++) br[j] = Bs[kk][tx*TN + j];
            #pragma unroll
            for (int i = 0; i < TM; i++)
                #pragma unroll
                for (int j = 0; j < TN; j++)
                    acc[i][j] += ar[i] * br[j];
        }
        __syncthreads();
    }

    if (A2 != nullptr) {
        for (int k0 = 0; k0 < K2; k0 += BK) {
            #pragma unroll
            for (int i = tid; i < BM*BK; i += NT) {
                int r = i / BK, c = i % BK;
                As[c][r] = A2[(long long)(m0 + r) * K2 + (k0 + c)];
            }
            #pragma unroll
            for (int i = tid; i < BK*BN; i += NT) {
                int r = i / BN, c = i % BN;
                Bs[r][c] = B2[(long long)(k0 + r) * N + (n0 + c)];
            }
            __syncthreads();
            #pragma unroll
            for (int kk = 0; kk < BK; kk++) {
                #pragma unroll
                for (int i = 0; i < TM; i++) ar[i] = As[kk][ty*TM + i];
                #pragma unroll
                for (int j = 0; j < TN; j++) br[j] = Bs[kk][tx*TN + j];
                #pragma unroll
                for (int i = 0; i < TM; i++)
                    #pragma unroll
                    for (int j = 0; j < TN; j++)
                        acc[i][j] += ar[i] * br[j];
            }
            __syncthreads();
        }
    }

    #pragma unroll
    for (int i = 0; i < TM; i++) {
        long long row = (long long)(m0 + ty*TM + i) * N + n0 + tx*TN;
        #pragma unroll
        for (int j = 0; j < TN; j++) C[row + j] = acc[i][j];
    }
}

// ----------------------------- rope cos/sin table --------------------------
__global__ void rope_table_kernel() {
    int s = blockIdx.x;        // 0..SEQ-1
    int i = threadIdx.x;       // 0..31
    double invf = exp(-(double)i * (log(10000.0) / 32.0));
    double ang  = (double)s * invf;
    g_cs_tab[s*32 + i] = make_float2((float)cos(ang), (float)sin(ang));
}

// --------------- RoPE + Hadamard phase + layout change (token->head) -------
__global__ void rope_phase_kernel() {
    long long idx = (long long)blockIdx.x * blockDim.x + threadIdx.x;
    if (idx >= (long long)NTOK * HID) return;
    int d = (int)(idx & 63);
    int h = (int)((idx >> 6) & 15);
    int t = (int)(idx >> 10);
    int b = t >> 11;            // SEQ = 2048
    int s = t & (SEQ - 1);
    int step = s & 3;
    float sgn = hsign(step, d);

    long long off  = idx;                         // token-major offset == idx
    long long poff = (d < 32) ? off + 32 : off - 32;
    int i = d & 31;
    float2 cs = g_cs_tab[s*32 + i];

    float qv = g_Q[off], qp = g_Q[poff];
    float kv = g_K[off], kp = g_K[poff];
    float qr = (d < 32) ? (qv*cs.x - qp*cs.y) : (qv*cs.x + qp*cs.y);
    float kr = (d < 32) ? (kv*cs.x - kp*cs.y) : (kv*cs.x + kp*cs.y);

    int bh = b*NH + h;
    long long hoff = (long long)(bh*SEQ + s) * HD + d;
    g_Qa[hoff] = qr * sgn * 0.125f;   // * inv_sqrt_d
    g_Ks[hoff] = kr * sgn * 0.5f;     // * 1/sqrt(kf)
    g_Vs[hoff] = g_V[off] * sgn * 0.5f;
}

// ------------------- full_K (transposed) / full_V per slot -----------------
__global__ void reduce_full_kernel() {
    int idx = blockIdx.x * blockDim.x + threadIdx.x;   // NBH*NS*HD = 1M
    if (idx >= NBH*NS*HD) return;
    int d    = idx & 63;
    int slot = (idx >> 6) & (NS - 1);
    int bh   = idx >> 15;     // 6 + 9
    long long base = (long long)(bh*SEQ + slot*KF) * HD + d;
    float sk = 0.f, sv = 0.f;
    #pragma unroll
    for (int j = 0; j < KF; j++) { sk += g_Ks[base + j*HD]; sv += g_Vs[base + j*HD]; }
    g_fullV[idx] = sv;                                  // [bh][slot][d]
    g_fullKT[((long long)bh*HD + d)*NS + slot] = sk;    // [bh][d][slot]
}

// --------- softmax per query (one warp), with current-slot override --------
__global__ void softmax_kernel() {
    int warp = (blockIdx.x * blockDim.x + threadIdx.x) >> 5;
    int lane = threadIdx.x & 31;
    if (warp >= NBH*SEQ) return;
    int bh = warp / SEQ;
    int q  = warp - bh*SEQ;
    int slot = q >> 2, step = q & 3;

    long long qoff = (long long)warp * HD;   // (bh*SEQ+q)*HD
    float qa0 = g_Qa[qoff + lane];
    float qa1 = g_Qa[qoff + lane + 32];

    // current partial K = cumsum of phase'd K rows within the slot
    long long krow = (long long)(bh*SEQ + slot*KF) * HD;
    float pk0 = 0.f, pk1 = 0.f;
    for (int j = 0; j <= step; j++) {
        pk0 += g_Ks[krow + j*HD + lane];
        pk1 += g_Ks[krow + j*HD + lane + 32];
    }
    float cs = qa0*pk0 + qa1*pk1;
    #pragma unroll
    for (int o = 16; o; o >>= 1) cs += __shfl_xor_sync(0xFFFFFFFFu, cs, o);

    float* row = g_scores + (long long)bh*SEQ*NS + (long long)q*NS;

    float m = cs;
    for (int s = lane; s < slot; s += 32) m = fmaxf(m, row[s]);
    #pragma unroll
    for (int o = 16; o; o >>= 1) m = fmaxf(m, __shfl_xor_sync(0xFFFFFFFFu, m, o));

    float e_cs = expf(cs - m);
    float lsum = 0.f;
    for (int s = lane; s < slot; s += 32) {
        float e = expf(row[s] - m);
        row[s] = e;
        lsum += e;
    }
    #pragma unroll
    for (int o = 16; o; o >>= 1) lsum += __shfl_xor_sync(0xFFFFFFFFu, lsum, o);
    float inv = 1.0f / (lsum + e_cs);

    for (int s = lane; s < NS; s += 32) {
        float w;
        if (s < slot)       w = row[s] * inv;
        else if (s == slot) w = e_cs * inv;
        else                w = 0.0f;
        row[s] = w;
    }
    if (lane == 0) g_wcurr[warp] = e_cs * inv;
}

// --- current-slot V correction + output phase + head-major -> token-major --
__global__ void fixup_kernel() {
    int bhq = blockIdx.x;          // NBH*SEQ
    int d = threadIdx.x;           // 64
    int bh = bhq >> 11;            // /SEQ
    int q  = bhq & (SEQ - 1);
    int slot = q >> 2, step = q & 3;

    float out = g_Ohead[(long long)bhq * HD + d];
    long long vrow = (long long)(bh*SEQ + slot*KF) * HD + d;
    float pv = 0.f;
    for (int j = 0; j <= step; j++) pv += g_Vs[vrow + j*HD];
    float fv = g_fullV[((long long)bh*NS + slot) * HD + d];
    float wc = g_wcurr[bhq];
    float val = (out + wc * (pv - fv)) * hsign(step, d) * 2.0f;  // * var_scale

    int b = bh >> 4, h = bh & 15;
    int t = b*SEQ + q;
    g_Otok[(long long)t*HID + h*HD + d] = val;
}

// --------------------------------- launcher --------------------------------
extern "C" void kernel_launch(void* const* d_in, const int* in_sizes, int n_in,
                              void* d_out, int out_size)
{
    (void)in_sizes; (void)n_in; (void)out_size;
    const float* X  = (const float*)d_in[0];
    const float* Wq = (const float*)d_in[1];
    const float* Wk = (const float*)d_in[2];
    const float* Wv = (const float*)d_in[3];
    const float* Wo = (const float*)d_in[4];
    const float* Aq = (const float*)d_in[5];
    const float* Bq = (const float*)d_in[6];
    const float* Av = (const float*)d_in[7];
    const float* Bv = (const float*)d_in[8];
    const float* Ao = (const float*)d_in[9];
    const float* Bo = (const float*)d_in[10];
    float* Y = (float*)d_out;

    float *pQ, *pK, *pV, *pXAq, *pXAv, *pXAo, *pQa, *pKT, *pFV, *pSc, *pOh, *pOt;
    cudaGetSymbolAddress((void**)&pQ,   g_Q);
    cudaGetSymbolAddress((void**)&pK,   g_K);
    cudaGetSymbolAddress((void**)&pV,   g_V);
    cudaGetSymbolAddress((void**)&pXAq, g_XAq);
    cudaGetSymbolAddress((void**)&pXAv, g_XAv);
    cudaGetSymbolAddress((void**)&pXAo, g_XAo);
    cudaGetSymbolAddress((void**)&pQa,  g_Qa);
    cudaGetSymbolAddress((void**)&pKT,  g_fullKT);
    cudaGetSymbolAddress((void**)&pFV,  g_fullV);
    cudaGetSymbolAddress((void**)&pSc,  g_scores);
    cudaGetSymbolAddress((void**)&pOh,  g_Ohead);
    cudaGetSymbolAddress((void**)&pOt,  g_Otok);

    const int NT_BIG = 256;

    // 1) LoRA stage 1: XAq = X @ Aq, XAv = X @ Av   (M=4096, N=64, K=1024)
    {
        dim3 grid(LR/64, NTOK/128, 1);
        sgemm<128,64,8,8,4><<<grid, NT_BIG>>>(X, Aq, pXAq, NTOK, LR, HID,
                                              0,0,0, nullptr, nullptr, 0, 0);
        sgemm<128,64,8,8,4><<<grid, NT_BIG>>>(X, Av, pXAv, NTOK, LR, HID,
                                              0,0,0, nullptr, nullptr, 0, 0);
    }
    // 2) Projections (M=4096, N=1024, K=1024), Q/V fused with LoRA stage 2
    {
        dim3 grid(HID/128, NTOK/128, 1);
        sgemm<128,128,8,8,8><<<grid, NT_BIG>>>(X, Wq, pQ, NTOK, HID, HID,
                                               0,0,0, pXAq, Bq, LR, 0);
        sgemm<128,128,8,8,8><<<grid, NT_BIG>>>(X, Wk, pK, NTOK, HID, HID,
                                               0,0,0, nullptr, nullptr, 0, 0);
        sgemm<128,128,8,8,8><<<grid, NT_BIG>>>(X, Wv, pV, NTOK, HID, HID,
                                               0,0,0, pXAv, Bv, LR, 0);
    }
    // 3) RoPE + phase folding + layout change
    rope_table_kernel<<<SEQ, 32>>>();
    {
        long long tot = (long long)NTOK * HID;
        rope_phase_kernel<<<(unsigned)((tot + 255) / 256), 256>>>();
    }
    // 4) full_K (transposed) / full_V per slot
    reduce_full_kernel<<<(NBH*NS*HD + 255)/256, 256>>>();

    // 5) scores = Qa @ fullKT  (batched over 32 (b,h), causal tile skip)
    {
        dim3 grid(NS/128, SEQ/128, NBH);
        sgemm<128,128,8,8,8><<<grid, NT_BIG>>>(
            pQa, pKT, pSc, SEQ, NS, HD,
            (long long)SEQ*HD, (long long)HD*NS, (long long)SEQ*NS,
            nullptr, nullptr, 0, /*causal=*/1);
    }
    // 6) softmax with current-slot score override; masked weights -> 0
    softmax_kernel<<<(NBH*SEQ*32)/256, 256>>>();

    // 7) Ohead = W @ fullV  (batched, causal K-limit)
    {
        dim3 grid(HD/64, SEQ/128, NBH);
        sgemm<128,64,8,8,4><<<grid, NT_BIG>>>(
            pSc, pFV, pOh, SEQ, HD, NS,
            (long long)SEQ*NS, (long long)NS*HD, (long long)SEQ*HD,
            nullptr, nullptr, 0, /*causal=*/2);
    }
    // 8) current-slot V correction + output phase, to token-major
    fixup_kernel<<<NBH*SEQ, HD>>>();

    // 9) LoRA stage 1 for O, then Y = O @ Wo + XAo @ Bo
    {
        dim3 grid1(LR/64, NTOK/128, 1);
        sgemm<128,64,8,8,4><<<grid1, NT_BIG>>>(pOt, Ao, pXAo, NTOK, LR, HID,
                                               0,0,0, nullptr, nullptr, 0, 0);
        dim3 grid2(HID/128, NTOK/128, 1);
        sgemm<128,128,8,8,8><<<grid2, NT_BIG>>>(pOt, Wo, Y, NTOK, HID, HID,
                                                0,0,0, pXAo, Bo, LR, 0);
    }
}

// round 7
// speedup vs baseline: 1.5326x; 1.5326x over previous
#include <cuda_runtime.h>
#include <cuda_bf16.h>
#include <cstdint>
#include <cstddef>
#include <math.h>

// ---------------------------------------------------------------------------
// HoloKVAttention: QKV(+LoRA) proj via bf16x3 split-precision tensor-core GEMM,
// RoPE+Hadamard phase -> holographic KV attention (fp32) -> O proj(+LoRA, MMA).
//
// Shapes: B=2, S=2048, HIDDEN=1024, NUM_HEADS=16, HEAD_DIM=64, K_FACTOR=4,
//         LORA_R=64, ns = S/kf = 512.
// ---------------------------------------------------------------------------

#define HID   1024
#define NH    16
#define HD    64
#define KF    4
#define LR    64
#define BATCH 2
#define SEQ   2048
#define NTOK  (BATCH*SEQ)   // 4096
#define NS    (SEQ/KF)      // 512
#define NBH   (BATCH*NH)    // 32

// ------------------------- device scratch (static) -------------------------
__device__ float g_Q[NTOK*HID];
__device__ float g_K[NTOK*HID];
__device__ float g_V[NTOK*HID];
__device__ float g_XA[NTOK*LR];        // LoRA stage-1 output (reused q/v/o)
__device__ float g_Qa[NBH*SEQ*HD];     // rope'd, phase * inv_sqrt_d folded
__device__ float g_Ks[NBH*SEQ*HD];     // rope'd, phase * 0.5 folded
__device__ float g_Vs[NBH*SEQ*HD];     // phase * 0.5 folded
__device__ float g_fullKT[NBH*HD*NS];  // per (bh): [d][slot]
__device__ float g_fullV[NBH*NS*HD];   // per (bh): [slot][d]
__device__ float g_scores[(size_t)NBH*SEQ*NS];
__device__ float g_wcurr[NBH*SEQ];
__device__ float g_Ohead[NBH*SEQ*HD];
__device__ float g_Otok[NTOK*HID];
__device__ float2 g_cs_tab[SEQ*32];

// bf16x3 split buffers
__device__ __align__(16) __nv_bfloat16 g_Xs[NTOK*3*HID];      // [Xh|Xh|Xl], reused for O
__device__ __align__(16) __nv_bfloat16 g_Wsplit[3*HID*HID];   // [Wh;Wl;Wh]
__device__ __align__(16) __nv_bfloat16 g_Asplit[3*HID*LR];
__device__ __align__(16) __nv_bfloat16 g_Bsplit[3*LR*HID];
__device__ __align__(16) __nv_bfloat16 g_XAsplit[NTOK*3*LR];

// Hadamard CDMA sign: CDMA[step][dim] = H[step][dim%4]
__device__ __forceinline__ float hsign(int step, int col) {
    return ((0x6CA0 >> ((step << 2) | (col & 3))) & 1) ? -1.0f : 1.0f;
}

// --------------------------- bf16 split kernels ----------------------------
// A-operand pattern: dst[m][0:K]=hi, [K:2K]=hi, [2K:3K]=lo   (row-major M x 3K)
__global__ void split_hhl(const float* __restrict__ src,
                          __nv_bfloat16* __restrict__ dst, int M, int K) {
    int idx = blockIdx.x * blockDim.x + threadIdx.x;
    if (idx >= M * K) return;
    int m = idx / K, k = idx - m * K;
    float x = src[idx];
    __nv_bfloat16 h = __float2bfloat16(x);
    __nv_bfloat16 l = __float2bfloat16(x - __bfloat162float(h));
    long long base = (long long)m * (3 * K);
    dst[base + k] = h;
    dst[base + K + k] = h;
    dst[base + 2 * K + k] = l;
}
// B-operand pattern: rows [0:K]=hi, [K:2K]=lo, [2K:3K]=hi   (row-major 3K x N)
__global__ void split_hlh(const float* __restrict__ src,
                          __nv_bfloat16* __restrict__ dst, int KN) {
    int idx = blockIdx.x * blockDim.x + threadIdx.x;
    if (idx >= KN) return;
    float x = src[idx];
    __nv_bfloat16 h = __float2bfloat16(x);
    __nv_bfloat16 l = __float2bfloat16(x - __bfloat162float(h));
    dst[idx] = h;
    dst[KN + idx] = l;
    dst[2 * KN + idx] = h;
}

// ------------------------ bf16 tensor-core GEMM ----------------------------
// C[M,N] (fp32) = A[M,K] @ B[K,N], A/B bf16 row-major. accumulate: C += result.
template<int BM, int BN, int BK, int WM, int WN>
__global__ __launch_bounds__(WM*WN*32)
void mma_gemm(const __nv_bfloat16* __restrict__ A,
              const __nv_bfloat16* __restrict__ B,
              float* __restrict__ C, int M, int N, int K, int accumulate)
{
    constexpr int NTH = WM * WN * 32;
    constexpr int WTM = BM / WM, WTN = BN / WN;
    constexpr int MT = WTM / 16, NTt = WTN / 8;
    __shared__ __align__(16) __nv_bfloat16 As[BM][BK + 8];
    __shared__ __align__(16) __nv_bfloat16 Bs[BK][BN + 8];

    const int m0 = blockIdx.y * BM, n0 = blockIdx.x * BN;
    const int tid = threadIdx.x, lane = tid & 31;
    const int wid = tid >> 5;
    const int wm = wid / WN, wn = wid % WN;

    float acc[MT][NTt][4] = {};

    for (int k0 = 0; k0 < K; k0 += BK) {
        #pragma unroll
        for (int i = tid; i < BM * BK / 8; i += NTH) {
            int r = i / (BK / 8), c = (i % (BK / 8)) * 8;
            *(uint4*)&As[r][c] = *(const uint4*)&A[(long long)(m0 + r) * K + k0 + c];
        }
        #pragma unroll
        for (int i = tid; i < BK * BN / 8; i += NTH) {
            int r = i / (BN / 8), c = (i % (BN / 8)) * 8;
            *(uint4*)&Bs[r][c] = *(const uint4*)&B[(long long)(k0 + r) * N + n0 + c];
        }
        __syncthreads();
        #pragma unroll
        for (int ks = 0; ks < BK / 16; ks++) {
            uint32_t a[MT][4], b[NTt][2];
            #pragma unroll
            for (int mt = 0; mt < MT; mt++) {
                uint32_t s = (uint32_t)__cvta_generic_to_shared(
                    &As[wm*WTM + mt*16 + (lane & 15)][ks*16 + ((lane >> 4) << 3)]);
                asm volatile("ldmatrix.sync.aligned.m8n8.x4.shared.b16 {%0,%1,%2,%3}, [%4];"
                    : "=r"(a[mt][0]), "=r"(a[mt][1]), "=r"(a[mt][2]), "=r"(a[mt][3])
                    : "r"(s));
            }
            #pragma unroll
            for (int np = 0; np < NTt / 2; np++) {
                uint32_t s = (uint32_t)__cvta_generic_to_shared(
                    &Bs[ks*16 + (lane & 15)][wn*WTN + np*16 + ((lane >> 4) << 3)]);
                asm volatile("ldmatrix.sync.aligned.m8n8.x4.trans.shared.b16 {%0,%1,%2,%3}, [%4];"
                    : "=r"(b[np*2][0]), "=r"(b[np*2][1]),
                      "=r"(b[np*2+1][0]), "=r"(b[np*2+1][1])
                    : "r"(s));
            }
            #pragma unroll
            for (int mt = 0; mt < MT; mt++)
                #pragma unroll
                for (int nt = 0; nt < NTt; nt++)
                    asm volatile(
                        "mma.sync.aligned.m16n8k16.row.col.f32.bf16.bf16.f32 "
                        "{%0,%1,%2,%3}, {%4,%5,%6,%7}, {%8,%9}, {%0,%1,%2,%3};"
                        : "+f"(acc[mt][nt][0]), "+f"(acc[mt][nt][1]),
                          "+f"(acc[mt][nt][2]), "+f"(acc[mt][nt][3])
                        : "r"(a[mt][0]), "r"(a[mt][1]), "r"(a[mt][2]), "r"(a[mt][3]),
                          "r"(b[nt][0]), "r"(b[nt][1]));
        }
        __syncthreads();
    }

    #pragma unroll
    for (int mt = 0; mt < MT; mt++) {
        int row = m0 + wm*WTM + mt*16 + (lane >> 2);
        #pragma unroll
        for (int nt = 0; nt < NTt; nt++) {
            int col = n0 + wn*WTN + nt*8 + ((lane & 3) << 1);
            float2* p0 = (float2*)&C[(long long)row * N + col];
            float2* p1 = (float2*)&C[(long long)(row + 8) * N + col];
            float2 v0 = make_float2(acc[mt][nt][0], acc[mt][nt][1]);
            float2 v1 = make_float2(acc[mt][nt][2], acc[mt][nt][3]);
            if (accumulate) {
                float2 o0 = *p0, o1 = *p1;
                v0.x += o0.x; v0.y += o0.y; v1.x += o1.x; v1.y += o1.y;
            }
            *p0 = v0; *p1 = v1;
        }
    }
}

// ------------------------------ fp32 SGEMM ---------------------------------
// (kept for scores / PV attention GEMMs, with causal modes)
template<int BM, int BN, int BK, int TM, int TN>
__global__ __launch_bounds__((BM/TM)*(BN/TN))
void sgemm(const float* __restrict__ A, const float* __restrict__ B,
           float* __restrict__ C,
           int M, int N, int K,
           long long sAb, long long sBb, long long sCb,
           int causal)
{
    constexpr int NT = (BM/TM)*(BN/TN);
    __shared__ float As[BK][BM + 4];
    __shared__ float Bs[BK][BN];

    const int m0 = blockIdx.y * BM;
    const int n0 = blockIdx.x * BN;
    if (causal == 1 && n0 > ((m0 + BM - 1) >> 2)) return;
    int kend = K;
    if (causal == 2) {
        int kl = ((m0 + BM - 1) >> 2) + 1;
        kl = (kl + BK - 1) / BK * BK;
        if (kl < kend) kend = kl;
    }
    const long long batch = blockIdx.z;
    A += batch * sAb; B += batch * sBb; C += batch * sCb;

    const int tid = threadIdx.x;
    const int tx = tid % (BN/TN);
    const int ty = tid / (BN/TN);

    float acc[TM][TN];
    #pragma unroll
    for (int i = 0; i < TM; i++)
        #pragma unroll
        for (int j = 0; j < TN; j++) acc[i][j] = 0.0f;

    float ar[TM], br[TN];

    for (int k0 = 0; k0 < kend; k0 += BK) {
        #pragma unroll
        for (int i = tid; i < BM*BK; i += NT) {
            int r = i / BK, c = i % BK;
            As[c][r] = A[(long long)(m0 + r) * K + (k0 + c)];
        }
        #pragma unroll
        for (int i = tid; i < BK*BN; i += NT) {
            int r = i / BN, c = i % BN;
            Bs[r][c] = B[(long long)(k0 + r) * N + (n0 + c)];
        }
        __syncthreads();
        #pragma unroll
        for (int kk = 0; kk < BK; kk++) {
            #pragma unroll
            for (int i = 0; i < TM; i++) ar[i] = As[kk][ty*TM + i];
            #pragma unroll
            for (int j = 0; j < TN; j++) br[j] = Bs[kk][tx*TN + j];
            #pragma unroll
            for (int i = 0; i < TM; i++)
                #pragma unroll
                for (int j = 0; j < TN; j++)
                    acc[i][j] += ar[i] * br[j];
        }
        __syncthreads();
    }

    #pragma unroll
    for (int i = 0; i < TM; i++) {
        long long row = (long long)(m0 + ty*TM + i) * N + n0 + tx*TN;
        #pragma unroll
        for (int j = 0; j < TN; j++) C[row + j] = acc[i][j];
    }
}

// ----------------------------- rope cos/sin table --------------------------
__global__ void rope_table_kernel() {
    int s = blockIdx.x;
    int i = threadIdx.x;
    double invf = exp(-(double)i * (log(10000.0) / 32.0));
    double ang  = (double)s * invf;
    g_cs_tab[s*32 + i] = make_float2((float)cos(ang), (float)sin(ang));
}

// --------------- RoPE + Hadamard phase + layout change (token->head) -------
__global__ void rope_phase_kernel() {
    long long idx = (long long)blockIdx.x * blockDim.x + threadIdx.x;
    if (idx >= (long long)NTOK * HID) return;
    int d = (int)(idx & 63);
    int h = (int)((idx >> 6) & 15);
    int t = (int)(idx >> 10);
    int b = t >> 11;
    int s = t & (SEQ - 1);
    int step = s & 3;
    float sgn = hsign(step, d);

    long long off  = idx;
    long long poff = (d < 32) ? off + 32 : off - 32;
    int i = d & 31;
    float2 cs = g_cs_tab[s*32 + i];

    float qv = g_Q[off], qp = g_Q[poff];
    float kv = g_K[off], kp = g_K[poff];
    float qr = (d < 32) ? (qv*cs.x - qp*cs.y) : (qv*cs.x + qp*cs.y);
    float kr = (d < 32) ? (kv*cs.x - kp*cs.y) : (kv*cs.x + kp*cs.y);

    int bh = b*NH + h;
    long long hoff = (long long)(bh*SEQ + s) * HD + d;
    g_Qa[hoff] = qr * sgn * 0.125f;   // * inv_sqrt_d
    g_Ks[hoff] = kr * sgn * 0.5f;     // * 1/sqrt(kf)
    g_Vs[hoff] = g_V[off] * sgn * 0.5f;
}

// ------------------- full_K (transposed) / full_V per slot -----------------
__global__ void reduce_full_kernel() {
    int idx = blockIdx.x * blockDim.x + threadIdx.x;
    if (idx >= NBH*NS*HD) return;
    int d    = idx & 63;
    int slot = (idx >> 6) & (NS - 1);
    int bh   = idx >> 15;
    long long base = (long long)(bh*SEQ + slot*KF) * HD + d;
    float sk = 0.f, sv = 0.f;
    #pragma unroll
    for (int j = 0; j < KF; j++) { sk += g_Ks[base + j*HD]; sv += g_Vs[base + j*HD]; }
    g_fullV[idx] = sv;
    g_fullKT[((long long)bh*HD + d)*NS + slot] = sk;
}

// --------- softmax per query (one warp), with current-slot override --------
__global__ void softmax_kernel() {
    int warp = (blockIdx.x * blockDim.x + threadIdx.x) >> 5;
    int lane = threadIdx.x & 31;
    if (warp >= NBH*SEQ) return;
    int bh = warp / SEQ;
    int q  = warp - bh*SEQ;
    int slot = q >> 2, step = q & 3;

    long long qoff = (long long)warp * HD;
    float qa0 = g_Qa[qoff + lane];
    float qa1 = g_Qa[qoff + lane + 32];

    long long krow = (long long)(bh*SEQ + slot*KF) * HD;
    float pk0 = 0.f, pk1 = 0.f;
    for (int j = 0; j <= step; j++) {
        pk0 += g_Ks[krow + j*HD + lane];
        pk1 += g_Ks[krow + j*HD + lane + 32];
    }
    float cs = qa0*pk0 + qa1*pk1;
    #pragma unroll
    for (int o = 16; o; o >>= 1) cs += __shfl_xor_sync(0xFFFFFFFFu, cs, o);

    float* row = g_scores + (long long)bh*SEQ*NS + (long long)q*NS;

    float m = cs;
    for (int s = lane; s < slot; s += 32) m = fmaxf(m, row[s]);
    #pragma unroll
    for (int o = 16; o; o >>= 1) m = fmaxf(m, __shfl_xor_sync(0xFFFFFFFFu, m, o));

    float e_cs = expf(cs - m);
    float lsum = 0.f;
    for (int s = lane; s < slot; s += 32) {
        float e = expf(row[s] - m);
        row[s] = e;
        lsum += e;
    }
    #pragma unroll
    for (int o = 16; o; o >>= 1) lsum += __shfl_xor_sync(0xFFFFFFFFu, lsum, o);
    float inv = 1.0f / (lsum + e_cs);

    for (int s = lane; s < NS; s += 32) {
        float w;
        if (s < slot)       w = row[s] * inv;
        else if (s == slot) w = e_cs * inv;
        else                w = 0.0f;
        row[s] = w;
    }
    if (lane == 0) g_wcurr[warp] = e_cs * inv;
}

// --- current-slot V correction + output phase + head-major -> token-major --
__global__ void fixup_kernel() {
    int bhq = blockIdx.x;
    int d = threadIdx.x;
    int bh = bhq >> 11;
    int q  = bhq & (SEQ - 1);
    int slot = q >> 2, step = q & 3;

    float out = g_Ohead[(long long)bhq * HD + d];
    long long vrow = (long long)(bh*SEQ + slot*KF) * HD + d;
    float pv = 0.f;
    for (int j = 0; j <= step; j++) pv += g_Vs[vrow + j*HD];
    float fv = g_fullV[((long long)bh*NS + slot) * HD + d];
    float wc = g_wcurr[bhq];
    float val = (out + wc * (pv - fv)) * hsign(step, d) * 2.0f;

    int b = bh >> 4, h = bh & 15;
    int t = b*SEQ + q;
    g_Otok[(long long)t*HID + h*HD + d] = val;
}

// --------------------------------- launcher --------------------------------
extern "C" void kernel_launch(void* const* d_in, const int* in_sizes, int n_in,
                              void* d_out, int out_size)
{
    (void)in_sizes; (void)n_in; (void)out_size;
    const float* X  = (const float*)d_in[0];
    const float* Wq = (const float*)d_in[1];
    const float* Wk = (const float*)d_in[2];
    const float* Wv = (const float*)d_in[3];
    const float* Wo = (const float*)d_in[4];
    const float* Aq = (const float*)d_in[5];
    const float* Bq = (const float*)d_in[6];
    const float* Av = (const float*)d_in[7];
    const float* Bv = (const float*)d_in[8];
    const float* Ao = (const float*)d_in[9];
    const float* Bo = (const float*)d_in[10];
    float* Y = (float*)d_out;

    float *pQ, *pK, *pV, *pXA, *pQa, *pKT, *pFV, *pSc, *pOh, *pOt;
    __nv_bfloat16 *pXs, *pWs, *pAs, *pBs, *pXAs;
    cudaGetSymbolAddress((void**)&pQ,   g_Q);
    cudaGetSymbolAddress((void**)&pK,   g_K);
    cudaGetSymbolAddress((void**)&pV,   g_V);
    cudaGetSymbolAddress((void**)&pXA,  g_XA);
    cudaGetSymbolAddress((void**)&pQa,  g_Qa);
    cudaGetSymbolAddress((void**)&pKT,  g_fullKT);
    cudaGetSymbolAddress((void**)&pFV,  g_fullV);
    cudaGetSymbolAddress((void**)&pSc,  g_scores);
    cudaGetSymbolAddress((void**)&pOh,  g_Ohead);
    cudaGetSymbolAddress((void**)&pOt,  g_Otok);
    cudaGetSymbolAddress((void**)&pXs,  g_Xs);
    cudaGetSymbolAddress((void**)&pWs,  g_Wsplit);
    cudaGetSymbolAddress((void**)&pAs,  g_Asplit);
    cudaGetSymbolAddress((void**)&pBs,  g_Bsplit);
    cudaGetSymbolAddress((void**)&pXAs, g_XAsplit);

    const dim3 gridBig(HID/128, NTOK/128);      // 8 x 32 (MMA big GEMMs)
    const dim3 gridLora1(1, NTOK/64);           // stage-1: N=64
    const int SPLIT_T = 256;

    // ---- split X once ----
    split_hhl<<<(NTOK*HID + SPLIT_T-1)/SPLIT_T, SPLIT_T>>>(X, pXs, NTOK, HID);

    // ---- Q projection + LoRA ----
    split_hlh<<<(HID*HID + SPLIT_T-1)/SPLIT_T, SPLIT_T>>>(Wq, pWs, HID*HID);
    mma_gemm<128,128,32,2,4><<<gridBig, 256>>>(pXs, pWs, pQ, NTOK, HID, 3*HID, 0);
    split_hlh<<<(HID*LR + SPLIT_T-1)/SPLIT_T, SPLIT_T>>>(Aq, pAs, HID*LR);
    mma_gemm<64,64,32,2,2><<<gridLora1, 128>>>(pXs, pAs, pXA, NTOK, LR, 3*HID, 0);
    split_hhl<<<(NTOK*LR + SPLIT_T-1)/SPLIT_T, SPLIT_T>>>(pXA, pXAs, NTOK, LR);
    split_hlh<<<(LR*HID + SPLIT_T-1)/SPLIT_T, SPLIT_T>>>(Bq, pBs, LR*HID);
    mma_gemm<128,128,32,2,4><<<gridBig, 256>>>(pXAs, pBs, pQ, NTOK, HID, 3*LR, 1);

    // ---- K projection ----
    split_hlh<<<(HID*HID + SPLIT_T-1)/SPLIT_T, SPLIT_T>>>(Wk, pWs, HID*HID);
    mma_gemm<128,128,32,2,4><<<gridBig, 256>>>(pXs, pWs, pK, NTOK, HID, 3*HID, 0);

    // ---- V projection + LoRA ----
    split_hlh<<<(HID*HID + SPLIT_T-1)/SPLIT_T, SPLIT_T>>>(Wv, pWs, HID*HID);
    mma_gemm<128,128,32,2,4><<<gridBig, 256>>>(pXs, pWs, pV, NTOK, HID, 3*HID, 0);
    split_hlh<<<(HID*LR + SPLIT_T-1)/SPLIT_T, SPLIT_T>>>(Av, pAs, HID*LR);
    mma_gemm<64,64,32,2,2><<<gridLora1, 128>>>(pXs, pAs, pXA, NTOK, LR, 3*HID, 0);
    split_hhl<<<(NTOK*LR + SPLIT_T-1)/SPLIT_T, SPLIT_T>>>(pXA, pXAs, NTOK, LR);
    split_hlh<<<(LR*HID + SPLIT_T-1)/SPLIT_T, SPLIT_T>>>(Bv, pBs, LR*HID);
    mma_gemm<128,128,32,2,4><<<gridBig, 256>>>(pXAs, pBs, pV, NTOK, HID, 3*LR, 1);

    // ---- RoPE + phase folding + layout change ----
    rope_table_kernel<<<SEQ, 32>>>();
    {
        long long tot = (long long)NTOK * HID;
        rope_phase_kernel<<<(unsigned)((tot + 255) / 256), 256>>>();
    }
    reduce_full_kernel<<<(NBH*NS*HD + 255)/256, 256>>>();

    // ---- scores = Qa @ fullKT (batched, causal tile skip) ----
    {
        dim3 grid(NS/128, SEQ/128, NBH);
        sgemm<128,128,8,8,8><<<grid, 256>>>(
            pQa, pKT, pSc, SEQ, NS, HD,
            (long long)SEQ*HD, (long long)HD*NS, (long long)SEQ*NS,
            /*causal=*/1);
    }
    softmax_kernel<<<(NBH*SEQ*32)/256, 256>>>();

    // ---- Ohead = W @ fullV (batched, causal K-limit) ----
    {
        dim3 grid(HD/64, SEQ/128, NBH);
        sgemm<128,64,8,8,4><<<grid, 256>>>(
            pSc, pFV, pOh, SEQ, HD, NS,
            (long long)SEQ*NS, (long long)NS*HD, (long long)SEQ*HD,
            /*causal=*/2);
    }
    fixup_kernel<<<NBH*SEQ, HD>>>();

    // ---- O projection + LoRA (reuse g_Xs for split Otok) ----
    split_hhl<<<(NTOK*HID + SPLIT_T-1)/SPLIT_T, SPLIT_T>>>(pOt, pXs, NTOK, HID);
    split_hlh<<<(HID*HID + SPLIT_T-1)/SPLIT_T, SPLIT_T>>>(Wo, pWs, HID*HID);
    mma_gemm<128,128,32,2,4><<<gridBig, 256>>>(pXs, pWs, Y, NTOK, HID, 3*HID, 0);
    split_hlh<<<(HID*LR + SPLIT_T-1)/SPLIT_T, SPLIT_T>>>(Ao, pAs, HID*LR);
    mma_gemm<64,64,32,2,2><<<gridLora1, 128>>>(pXs, pAs, pXA, NTOK, LR, 3*HID, 0);
    split_hhl<<<(NTOK*LR + SPLIT_T-1)/SPLIT_T, SPLIT_T>>>(pXA, pXAs, NTOK, LR);
    split_hlh<<<(LR*HID + SPLIT_T-1)/SPLIT_T, SPLIT_T>>>(Bo, pBs, LR*HID);
    mma_gemm<128,128,32,2,4><<<gridBig, 256>>>(pXAs, pBs, Y, NTOK, HID, 3*LR, 1);
}

// round 8
// speedup vs baseline: 2.0162x; 1.3155x over previous
#include <cuda_runtime.h>
#include <cuda_bf16.h>
#include <cstdint>
#include <cstddef>
#include <math.h>

// ---------------------------------------------------------------------------
// HoloKVAttention: all GEMMs on tensor cores via bf16x3 split precision.
// Projections + LoRA + attention scores + PV all use a double-buffered
// cp.async bf16 MMA kernel. Split operands for attention are produced
// in-place by the rope/reduce/softmax kernels (no extra passes).
// ---------------------------------------------------------------------------

#define HID   1024
#define NH    16
#define HD    64
#define KF    4
#define LR    64
#define BATCH 2
#define SEQ   2048
#define NTOK  (BATCH*SEQ)   // 4096
#define NS    (SEQ/KF)      // 512
#define NBH   (BATCH*NH)    // 32

// ------------------------- device scratch (static) -------------------------
__device__ float g_Q[NTOK*HID];
__device__ float g_K[NTOK*HID];
__device__ float g_V[NTOK*HID];
__device__ float g_XA[NTOK*LR];
__device__ float g_Ks[NBH*SEQ*HD];     // rope'd, phase * 0.5 folded (fp32)
__device__ float g_Vs[NBH*SEQ*HD];     // phase * 0.5 folded (fp32)
__device__ float g_fullV[NBH*NS*HD];   // fp32, for fixup
__device__ float g_scores[(size_t)NBH*SEQ*NS];  // raw scores (fp32 scratch)
__device__ float g_wcurr[NBH*SEQ];
__device__ float g_Ohead[NBH*SEQ*HD];
__device__ float g_Otok[NTOK*HID];
__device__ float2 g_cs_tab[SEQ*32];

// bf16 split operand buffers
__device__ __align__(16) __nv_bfloat16 g_Xs[NTOK*3*HID];        // [Xh|Xh|Xl]
__device__ __align__(16) __nv_bfloat16 g_Wsplit[3*HID*HID];     // [Wh;Wl;Wh]
__device__ __align__(16) __nv_bfloat16 g_Asplit[3*HID*LR];
__device__ __align__(16) __nv_bfloat16 g_Bsplit[3*LR*HID];
__device__ __align__(16) __nv_bfloat16 g_XAsplit[NTOK*3*LR];
__device__ __align__(16) __nv_bfloat16 g_Qas[(size_t)NBH*SEQ*3*HD];      // A: [Qh|Qh|Ql] rows, K=192
__device__ __align__(16) __nv_bfloat16 g_KTs[(size_t)NBH*3*HD*NS];       // B: rows [Kh;Kl;Kh], N=NS
__device__ __align__(16) __nv_bfloat16 g_FVs[(size_t)NBH*3*NS*HD];       // B: interleaved [Vh;Vl;Vh] per slot
__device__ __align__(16) __nv_bfloat16 g_Ws[(size_t)NBH*SEQ*3*NS];       // A: interleaved (Wh,Wh,Wl) per slot

// Hadamard CDMA sign
__device__ __forceinline__ float hsign(int step, int col) {
    return ((0x6CA0 >> ((step << 2) | (col & 3))) & 1) ? -1.0f : 1.0f;
}

__device__ __forceinline__ void cp_async16(void* smem, const void* gmem) {
    uint32_t s = (uint32_t)__cvta_generic_to_shared(smem);
    asm volatile("cp.async.cg.shared.global [%0], [%1], 16;" :: "r"(s), "l"(gmem));
}

// --------------------------- bf16 split kernels ----------------------------
__global__ void split_hhl(const float* __restrict__ src,
                          __nv_bfloat16* __restrict__ dst, int M, int K) {
    int idx = blockIdx.x * blockDim.x + threadIdx.x;
    if (idx >= M * K) return;
    int m = idx / K, k = idx - m * K;
    float x = src[idx];
    __nv_bfloat16 h = __float2bfloat16(x);
    __nv_bfloat16 l = __float2bfloat16(x - __bfloat162float(h));
    long long base = (long long)m * (3 * K);
    dst[base + k] = h;
    dst[base + K + k] = h;
    dst[base + 2 * K + k] = l;
}
__global__ void split_hlh(const float* __restrict__ src,
                          __nv_bfloat16* __restrict__ dst, int KN) {
    int idx = blockIdx.x * blockDim.x + threadIdx.x;
    if (idx >= KN) return;
    float x = src[idx];
    __nv_bfloat16 h = __float2bfloat16(x);
    __nv_bfloat16 l = __float2bfloat16(x - __bfloat162float(h));
    dst[idx] = h;
    dst[KN + idx] = l;
    dst[2 * KN + idx] = h;
}

// --------------- double-buffered cp.async bf16 tensor-core GEMM ------------
// C[M,N] fp32 = A[M,K] @ B[K,N]; batched over blockIdx.z via element strides.
// causal: 0 none; 1 scores tile-skip (cols=slots, rows=queries);
//         2 PV K-limit (K interleaved 3 per slot).
template<int BM, int BN, int BK, int WM, int WN>
__global__ __launch_bounds__(WM*WN*32)
void mma_gemm(const __nv_bfloat16* __restrict__ A,
              const __nv_bfloat16* __restrict__ B,
              float* __restrict__ C, int M, int N, int K,
              long long sA, long long sB, long long sC,
              int accumulate, int causal)
{
    constexpr int NTH = WM * WN * 32;
    constexpr int WTM = BM / WM, WTN = BN / WN;
    constexpr int MT = WTM / 16, NTt = WTN / 8;
    __shared__ __align__(16) __nv_bfloat16 As[2][BM][BK + 8];
    __shared__ __align__(16) __nv_bfloat16 Bs[2][BK][BN + 8];

    const int m0 = blockIdx.y * BM, n0 = blockIdx.x * BN;
    if (causal == 1 && n0 > ((m0 + BM - 1) >> 2)) return;
    int kend = K;
    if (causal == 2) {
        int slot_max = (m0 + BM - 1) >> 2;
        int kl = 3 * (slot_max + 1);
        kl = (kl + BK - 1) / BK * BK;
        if (kl < kend) kend = kl;
    }
    const int KT = kend / BK;

    const long long z = blockIdx.z;
    A += z * sA; B += z * sB; C += z * sC;

    const int tid = threadIdx.x, lane = tid & 31;
    const int wid = tid >> 5;
    const int wm = wid / WN, wn = wid % WN;

    float acc[MT][NTt][4] = {};

    // stage loader
    auto load_stage = [&](int kt, int st) {
        const int k0 = kt * BK;
        #pragma unroll
        for (int i = tid; i < BM * BK / 8; i += NTH) {
            int r = i / (BK / 8), c = (i % (BK / 8)) * 8;
            cp_async16(&As[st][r][c], &A[(long long)(m0 + r) * K + k0 + c]);
        }
        #pragma unroll
        for (int i = tid; i < BK * BN / 8; i += NTH) {
            int r = i / (BN / 8), c = (i % (BN / 8)) * 8;
            cp_async16(&Bs[st][r][c], &B[(long long)(k0 + r) * N + n0 + c]);
        }
        asm volatile("cp.async.commit_group;");
    };

    load_stage(0, 0);

    for (int kt = 0; kt < KT; kt++) {
        const int st = kt & 1;
        if (kt + 1 < KT) {
            load_stage(kt + 1, st ^ 1);
            asm volatile("cp.async.wait_group 1;");
        } else {
            asm volatile("cp.async.wait_group 0;");
        }
        __syncthreads();

        #pragma unroll
        for (int ks = 0; ks < BK / 16; ks++) {
            uint32_t a[MT][4], b[NTt][2];
            #pragma unroll
            for (int mt = 0; mt < MT; mt++) {
                uint32_t s = (uint32_t)__cvta_generic_to_shared(
                    &As[st][wm*WTM + mt*16 + (lane & 15)][ks*16 + ((lane >> 4) << 3)]);
                asm volatile("ldmatrix.sync.aligned.m8n8.x4.shared.b16 {%0,%1,%2,%3}, [%4];"
                    : "=r"(a[mt][0]), "=r"(a[mt][1]), "=r"(a[mt][2]), "=r"(a[mt][3])
                    : "r"(s));
            }
            #pragma unroll
            for (int np = 0; np < NTt / 2; np++) {
                uint32_t s = (uint32_t)__cvta_generic_to_shared(
                    &Bs[st][ks*16 + (lane & 15)][wn*WTN + np*16 + ((lane >> 4) << 3)]);
                asm volatile("ldmatrix.sync.aligned.m8n8.x4.trans.shared.b16 {%0,%1,%2,%3}, [%4];"
                    : "=r"(b[np*2][0]), "=r"(b[np*2][1]),
                      "=r"(b[np*2+1][0]), "=r"(b[np*2+1][1])
                    : "r"(s));
            }
            #pragma unroll
            for (int mt = 0; mt < MT; mt++)
                #pragma unroll
                for (int nt = 0; nt < NTt; nt++)
                    asm volatile(
                        "mma.sync.aligned.m16n8k16.row.col.f32.bf16.bf16.f32 "
                        "{%0,%1,%2,%3}, {%4,%5,%6,%7}, {%8,%9}, {%0,%1,%2,%3};"
                        : "+f"(acc[mt][nt][0]), "+f"(acc[mt][nt][1]),
                          "+f"(acc[mt][nt][2]), "+f"(acc[mt][nt][3])
                        : "r"(a[mt][0]), "r"(a[mt][1]), "r"(a[mt][2]), "r"(a[mt][3]),
                          "r"(b[nt][0]), "r"(b[nt][1]));
        }
        __syncthreads();
    }

    #pragma unroll
    for (int mt = 0; mt < MT; mt++) {
        int row = m0 + wm*WTM + mt*16 + (lane >> 2);
        #pragma unroll
        for (int nt = 0; nt < NTt; nt++) {
            int col = n0 + wn*WTN + nt*8 + ((lane & 3) << 1);
            float2* p0 = (float2*)&C[(long long)row * N + col];
            float2* p1 = (float2*)&C[(long long)(row + 8) * N + col];
            float2 v0 = make_float2(acc[mt][nt][0], acc[mt][nt][1]);
            float2 v1 = make_float2(acc[mt][nt][2], acc[mt][nt][3]);
            if (accumulate) {
                float2 o0 = *p0, o1 = *p1;
                v0.x += o0.x; v0.y += o0.y; v1.x += o1.x; v1.y += o1.y;
            }
            *p0 = v0; *p1 = v1;
        }
    }
}

// ----------------------------- rope cos/sin table --------------------------
__global__ void rope_table_kernel() {
    int s = blockIdx.x;
    int i = threadIdx.x;
    double invf = exp(-(double)i * (log(10000.0) / 32.0));
    double ang  = (double)s * invf;
    g_cs_tab[s*32 + i] = make_float2((float)cos(ang), (float)sin(ang));
}

// ------ RoPE + Hadamard phase + layout change; emits Qa split directly -----
__global__ void rope_phase_kernel() {
    long long idx = (long long)blockIdx.x * blockDim.x + threadIdx.x;
    if (idx >= (long long)NTOK * HID) return;
    int d = (int)(idx & 63);
    int h = (int)((idx >> 6) & 15);
    int t = (int)(idx >> 10);
    int b = t >> 11;
    int s = t & (SEQ - 1);
    int step = s & 3;
    float sgn = hsign(step, d);

    long long off  = idx;
    long long poff = (d < 32) ? off + 32 : off - 32;
    int i = d & 31;
    float2 cs = g_cs_tab[s*32 + i];

    float qv = g_Q[off], qp = g_Q[poff];
    float kv = g_K[off], kp = g_K[poff];
    float qr = (d < 32) ? (qv*cs.x - qp*cs.y) : (qv*cs.x + qp*cs.y);
    float kr = (d < 32) ? (kv*cs.x - kp*cs.y) : (kv*cs.x + kp*cs.y);

    int bh = b*NH + h;
    long long hoff = (long long)(bh*SEQ + s) * HD + d;
    float qa = qr * sgn * 0.125f;       // * inv_sqrt_d
    g_Ks[hoff] = kr * sgn * 0.5f;       // * 1/sqrt(kf)
    g_Vs[hoff] = g_V[off] * sgn * 0.5f;

    // Qa split: row layout [Qh(64) | Qh(64) | Ql(64)]
    __nv_bfloat16 qh = __float2bfloat16(qa);
    __nv_bfloat16 ql = __float2bfloat16(qa - __bfloat162float(qh));
    long long qbase = (long long)(bh*SEQ + s) * (3*HD) + d;
    g_Qas[qbase]          = qh;
    g_Qas[qbase + HD]     = qh;
    g_Qas[qbase + 2*HD]   = ql;
}

// ---- full_K / full_V per slot; emits split B-operands for both GEMMs ------
__global__ void reduce_full_kernel() {
    int idx = blockIdx.x * blockDim.x + threadIdx.x;
    if (idx >= NBH*NS*HD) return;
    int d    = idx & 63;
    int slot = (idx >> 6) & (NS - 1);
    int bh   = idx >> 15;
    long long base = (long long)(bh*SEQ + slot*KF) * HD + d;
    float sk = 0.f, sv = 0.f;
    #pragma unroll
    for (int j = 0; j < KF; j++) { sk += g_Ks[base + j*HD]; sv += g_Vs[base + j*HD]; }
    g_fullV[idx] = sv;

    // fullKT split B: rows [Kh(64); Kl(64); Kh(64)] x cols NS
    __nv_bfloat16 kh = __float2bfloat16(sk);
    __nv_bfloat16 kl = __float2bfloat16(sk - __bfloat162float(kh));
    long long ktb = ((long long)bh * (3*HD) + d) * NS + slot;
    g_KTs[ktb]             = kh;
    g_KTs[ktb + (long long)HD * NS]   = kl;
    g_KTs[ktb + (long long)2*HD * NS] = kh;

    // fullV split B, K interleaved per slot: rows (3s, 3s+1, 3s+2) = (Vh, Vl, Vh)
    __nv_bfloat16 vh = __float2bfloat16(sv);
    __nv_bfloat16 vl = __float2bfloat16(sv - __bfloat162float(vh));
    long long fvb = ((long long)bh * (3*NS) + 3*slot) * HD + d;
    g_FVs[fvb]        = vh;
    g_FVs[fvb + HD]   = vl;
    g_FVs[fvb + 2*HD] = vh;
}

// --------- softmax per query (one warp); emits W split (interleaved) -------
__global__ void softmax_kernel() {
    int warp = (blockIdx.x * blockDim.x + threadIdx.x) >> 5;
    int lane = threadIdx.x & 31;
    if (warp >= NBH*SEQ) return;
    int bh = warp / SEQ;
    int q  = warp - bh*SEQ;
    int slot = q >> 2, step = q & 3;

    // reconstruct Qa (hi+lo) from split
    const __nv_bfloat16* qrow = g_Qas + (long long)warp * (3*HD);
    float qa0 = __bfloat162float(qrow[lane])      + __bfloat162float(qrow[2*HD + lane]);
    float qa1 = __bfloat162float(qrow[32 + lane]) + __bfloat162float(qrow[2*HD + 32 + lane]);

    long long krow = (long long)(bh*SEQ + slot*KF) * HD;
    float pk0 = 0.f, pk1 = 0.f;
    for (int j = 0; j <= step; j++) {
        pk0 += g_Ks[krow + j*HD + lane];
        pk1 += g_Ks[krow + j*HD + lane + 32];
    }
    float cs = qa0*pk0 + qa1*pk1;
    #pragma unroll
    for (int o = 16; o; o >>= 1) cs += __shfl_xor_sync(0xFFFFFFFFu, cs, o);

    float* row = g_scores + (long long)bh*SEQ*NS + (long long)q*NS;

    float m = cs;
    for (int s = lane; s < slot; s += 32) m = fmaxf(m, row[s]);
    #pragma unroll
    for (int o = 16; o; o >>= 1) m = fmaxf(m, __shfl_xor_sync(0xFFFFFFFFu, m, o));

    float e_cs = expf(cs - m);
    float lsum = 0.f;
    for (int s = lane; s < slot; s += 32) {
        float e = expf(row[s] - m);
        row[s] = e;
        lsum += e;
    }
    #pragma unroll
    for (int o = 16; o; o >>= 1) lsum += __shfl_xor_sync(0xFFFFFFFFu, lsum, o);
    float inv = 1.0f / (lsum + e_cs);

    // write W split interleaved: k=3s -> Wh, 3s+1 -> Wh, 3s+2 -> Wl
    __nv_bfloat16* wrow = g_Ws + (long long)warp * (3*NS);
    for (int s = lane; s < NS; s += 32) {
        float w;
        if (s < slot)       w = row[s] * inv;
        else if (s == slot) w = e_cs * inv;
        else                w = 0.0f;
        __nv_bfloat16 h = __float2bfloat16(w);
        __nv_bfloat16 l = __float2bfloat16(w - __bfloat162float(h));
        wrow[3*s]     = h;
        wrow[3*s + 1] = h;
        wrow[3*s + 2] = l;
    }
    if (lane == 0) g_wcurr[warp] = e_cs * inv;
}

// --- current-slot V correction + output phase + head-major -> token-major --
__global__ void fixup_kernel() {
    int bhq = blockIdx.x;
    int d = threadIdx.x;
    int bh = bhq >> 11;
    int q  = bhq & (SEQ - 1);
    int slot = q >> 2, step = q & 3;

    float out = g_Ohead[(long long)bhq * HD + d];
    long long vrow = (long long)(bh*SEQ + slot*KF) * HD + d;
    float pv = 0.f;
    for (int j = 0; j <= step; j++) pv += g_Vs[vrow + j*HD];
    float fv = g_fullV[((long long)bh*NS + slot) * HD + d];
    float wc = g_wcurr[bhq];
    float val = (out + wc * (pv - fv)) * hsign(step, d) * 2.0f;

    int b = bh >> 4, h = bh & 15;
    int t = b*SEQ + q;
    g_Otok[(long long)t*HID + h*HD + d] = val;
}

// --------------------------------- launcher --------------------------------
extern "C" void kernel_launch(void* const* d_in, const int* in_sizes, int n_in,
                              void* d_out, int out_size)
{
    (void)in_sizes; (void)n_in; (void)out_size;
    const float* X  = (const float*)d_in[0];
    const float* Wq = (const float*)d_in[1];
    const float* Wk = (const float*)d_in[2];
    const float* Wv = (const float*)d_in[3];
    const float* Wo = (const float*)d_in[4];
    const float* Aq = (const float*)d_in[5];
    const float* Bq = (const float*)d_in[6];
    const float* Av = (const float*)d_in[7];
    const float* Bv = (const float*)d_in[8];
    const float* Ao = (const float*)d_in[9];
    const float* Bo = (const float*)d_in[10];
    float* Y = (float*)d_out;

    float *pQ, *pK, *pV, *pXA, *pFV, *pSc, *pOh, *pOt;
    __nv_bfloat16 *pXs, *pWs, *pAs, *pBs, *pXAs, *pQas, *pKTs, *pFVs, *pWw;
    cudaGetSymbolAddress((void**)&pQ,   g_Q);
    cudaGetSymbolAddress((void**)&pK,   g_K);
    cudaGetSymbolAddress((void**)&pV,   g_V);
    cudaGetSymbolAddress((void**)&pXA,  g_XA);
    cudaGetSymbolAddress((void**)&pFV,  g_fullV);
    cudaGetSymbolAddress((void**)&pSc,  g_scores);
    cudaGetSymbolAddress((void**)&pOh,  g_Ohead);
    cudaGetSymbolAddress((void**)&pOt,  g_Otok);
    cudaGetSymbolAddress((void**)&pXs,  g_Xs);
    cudaGetSymbolAddress((void**)&pWs,  g_Wsplit);
    cudaGetSymbolAddress((void**)&pAs,  g_Asplit);
    cudaGetSymbolAddress((void**)&pBs,  g_Bsplit);
    cudaGetSymbolAddress((void**)&pXAs, g_XAsplit);
    cudaGetSymbolAddress((void**)&pQas, g_Qas);
    cudaGetSymbolAddress((void**)&pKTs, g_KTs);
    cudaGetSymbolAddress((void**)&pFVs, g_FVs);
    cudaGetSymbolAddress((void**)&pWw,  g_Ws);

    const dim3 gridBig(HID/128, NTOK/128);   // 8 x 32
    const dim3 gridLora1(1, NTOK/64);
    const int SPLIT_T = 256;

    // ---- split X once ----
    split_hhl<<<(NTOK*HID + SPLIT_T-1)/SPLIT_T, SPLIT_T>>>(X, pXs, NTOK, HID);

    // ---- Q projection + LoRA ----
    split_hlh<<<(HID*HID + SPLIT_T-1)/SPLIT_T, SPLIT_T>>>(Wq, pWs, HID*HID);
    mma_gemm<128,128,32,2,4><<<gridBig, 256>>>(pXs, pWs, pQ, NTOK, HID, 3*HID, 0,0,0, 0, 0);
    split_hlh<<<(HID*LR + SPLIT_T-1)/SPLIT_T, SPLIT_T>>>(Aq, pAs, HID*LR);
    mma_gemm<64,64,32,2,2><<<gridLora1, 128>>>(pXs, pAs, pXA, NTOK, LR, 3*HID, 0,0,0, 0, 0);
    split_hhl<<<(NTOK*LR + SPLIT_T-1)/SPLIT_T, SPLIT_T>>>(pXA, pXAs, NTOK, LR);
    split_hlh<<<(LR*HID + SPLIT_T-1)/SPLIT_T, SPLIT_T>>>(Bq, pBs, LR*HID);
    mma_gemm<128,128,32,2,4><<<gridBig, 256>>>(pXAs, pBs, pQ, NTOK, HID, 3*LR, 0,0,0, 1, 0);

    // ---- K projection ----
    split_hlh<<<(HID*HID + SPLIT_T-1)/SPLIT_T, SPLIT_T>>>(Wk, pWs, HID*HID);
    mma_gemm<128,128,32,2,4><<<gridBig, 256>>>(pXs, pWs, pK, NTOK, HID, 3*HID, 0,0,0, 0, 0);

    // ---- V projection + LoRA ----
    split_hlh<<<(HID*HID + SPLIT_T-1)/SPLIT_T, SPLIT_T>>>(Wv, pWs, HID*HID);
    mma_gemm<128,128,32,2,4><<<gridBig, 256>>>(pXs, pWs, pV, NTOK, HID, 3*HID, 0,0,0, 0, 0);
    split_hlh<<<(HID*LR + SPLIT_T-1)/SPLIT_T, SPLIT_T>>>(Av, pAs, HID*LR);
    mma_gemm<64,64,32,2,2><<<gridLora1, 128>>>(pXs, pAs, pXA, NTOK, LR, 3*HID, 0,0,0, 0, 0);
    split_hhl<<<(NTOK*LR + SPLIT_T-1)/SPLIT_T, SPLIT_T>>>(pXA, pXAs, NTOK, LR);
    split_hlh<<<(LR*HID + SPLIT_T-1)/SPLIT_T, SPLIT_T>>>(Bv, pBs, LR*HID);
    mma_gemm<128,128,32,2,4><<<gridBig, 256>>>(pXAs, pBs, pV, NTOK, HID, 3*LR, 0,0,0, 1, 0);

    // ---- RoPE + phase folding (emits Qa split) ----
    rope_table_kernel<<<SEQ, 32>>>();
    {
        long long tot = (long long)NTOK * HID;
        rope_phase_kernel<<<(unsigned)((tot + 255) / 256), 256>>>();
    }
    reduce_full_kernel<<<(NBH*NS*HD + 255)/256, 256>>>();

    // ---- scores = Qa @ fullKT  (MMA, batched, causal tile-skip) ----
    {
        dim3 grid(NS/128, SEQ/128, NBH);
        mma_gemm<128,128,32,2,4><<<grid, 256>>>(
            pQas, pKTs, pSc, SEQ, NS, 3*HD,
            (long long)SEQ*3*HD, (long long)3*HD*NS, (long long)SEQ*NS,
            0, /*causal=*/1);
    }
    softmax_kernel<<<(NBH*SEQ*32)/256, 256>>>();

    // ---- Ohead = W @ fullV  (MMA, batched, causal K-limit) ----
    {
        dim3 grid(1, SEQ/128, NBH);
        mma_gemm<128,64,32,4,2><<<grid, 256>>>(
            pWw, pFVs, pOh, SEQ, HD, 3*NS,
            (long long)SEQ*3*NS, (long long)3*NS*HD, (long long)SEQ*HD,
            0, /*causal=*/2);
    }
    fixup_kernel<<<NBH*SEQ, HD>>>();

    // ---- O projection + LoRA ----
    split_hhl<<<(NTOK*HID + SPLIT_T-1)/SPLIT_T, SPLIT_T>>>(pOt, pXs, NTOK, HID);
    split_hlh<<<(HID*HID + SPLIT_T-1)/SPLIT_T, SPLIT_T>>>(Wo, pWs, HID*HID);
    mma_gemm<128,128,32,2,4><<<gridBig, 256>>>(pXs, pWs, Y, NTOK, HID, 3*HID, 0,0,0, 0, 0);
    split_hlh<<<(HID*LR + SPLIT_T-1)/SPLIT_T, SPLIT_T>>>(Ao, pAs, HID*LR);
    mma_gemm<64,64,32,2,2><<<gridLora1, 128>>>(pXs, pAs, pXA, NTOK, LR, 3*HID, 0,0,0, 0, 0);
    split_hhl<<<(NTOK*LR + SPLIT_T-1)/SPLIT_T, SPLIT_T>>>(pXA, pXAs, NTOK, LR);
    split_hlh<<<(LR*HID + SPLIT_T-1)/SPLIT_T, SPLIT_T>>>(Bo, pBs, LR*HID);
    mma_gemm<128,128,32,2,4><<<gridBig, 256>>>(pXAs, pBs, Y, NTOK, HID, 3*LR, 0,0,0, 1, 0);
}

// round 9
// speedup vs baseline: 2.2027x; 1.0925x over previous
#include <cuda_runtime.h>
#include <cuda_bf16.h>
#include <cstdint>
#include <cstddef>
#include <math.h>

// ---------------------------------------------------------------------------
// HoloKVAttention, all GEMMs bf16x3 split precision on tensor cores.
// R9: combined QKV GEMM (N=3072), BK=64 dynamic-smem pipeline, softmax
// causal-limited W writes.
// ---------------------------------------------------------------------------

#define HID   1024
#define NH    16
#define HD    64
#define KF    4
#define LR    64
#define BATCH 2
#define SEQ   2048
#define NTOK  (BATCH*SEQ)   // 4096
#define NS    (SEQ/KF)      // 512
#define NBH   (BATCH*NH)    // 32

// ------------------------- device scratch (static) -------------------------
__device__ float g_QKV[(size_t)NTOK*3*HID];   // [tok][Q(1024)|K(1024)|V(1024)]
__device__ float g_XA[NTOK*128];              // LoRA stage-1 out (q|v) or (o)
__device__ float g_Ks[NBH*SEQ*HD];
__device__ float g_Vs[NBH*SEQ*HD];
__device__ float g_fullV[NBH*NS*HD];
__device__ float g_scores[(size_t)NBH*SEQ*NS];
__device__ float g_wcurr[NBH*SEQ];
__device__ float g_Ohead[NBH*SEQ*HD];
__device__ float g_Otok[NTOK*HID];
__device__ float2 g_cs_tab[SEQ*32];

// bf16 split operand buffers
__device__ __align__(16) __nv_bfloat16 g_Xs[(size_t)NTOK*3*HID];     // [Xh|Xh|Xl]
__device__ __align__(16) __nv_bfloat16 g_Wqkv[(size_t)3*HID*3*HID];  // combined hlh, ld=3072
__device__ __align__(16) __nv_bfloat16 g_Wsplit[3*HID*HID];          // Wo hlh
__device__ __align__(16) __nv_bfloat16 g_AB[3*HID*128];              // [Aq|Av] or Ao hlh
__device__ __align__(16) __nv_bfloat16 g_Bsplit[3*LR*HID];           // Bq/Bv/Bo hlh
__device__ __align__(16) __nv_bfloat16 g_XAsplit[NTOK*2*3*LR];       // hhl x2, ld=384
__device__ __align__(16) __nv_bfloat16 g_Qas[(size_t)NBH*SEQ*3*HD];  // ld=192
__device__ __align__(16) __nv_bfloat16 g_KTs[(size_t)NBH*3*HD*NS];   // ld=NS
__device__ __align__(16) __nv_bfloat16 g_FVs[(size_t)NBH*3*NS*HD];   // interleaved, ld=HD
__device__ __align__(16) __nv_bfloat16 g_Ws[(size_t)NBH*SEQ*3*NS];   // ld=1536

__device__ __forceinline__ float hsign(int step, int col) {
    return ((0x6CA0 >> ((step << 2) | (col & 3))) & 1) ? -1.0f : 1.0f;
}

__device__ __forceinline__ void cp_async16(void* smem, const void* gmem) {
    uint32_t s = (uint32_t)__cvta_generic_to_shared(smem);
    asm volatile("cp.async.cg.shared.global [%0], [%1], 16;" :: "r"(s), "l"(gmem));
}

// --------------------------- bf16 split kernels ----------------------------
// A-operand: dst[m][0:K]=hi,[K:2K]=hi,[2K:3K]=lo  (row-major M x 3K)
__global__ void split_hhl(const float* __restrict__ src,
                          __nv_bfloat16* __restrict__ dst, int M, int K) {
    int idx = blockIdx.x * blockDim.x + threadIdx.x;
    if (idx >= M * K) return;
    int m = idx / K, k = idx - m * K;
    float x = src[idx];
    __nv_bfloat16 h = __float2bfloat16(x);
    __nv_bfloat16 l = __float2bfloat16(x - __bfloat162float(h));
    long long base = (long long)m * (3 * K);
    dst[base + k] = h; dst[base + K + k] = h; dst[base + 2*K + k] = l;
}
// B-operand: rows [0:K)=hi,[K:2K)=lo,[2K:3K)=hi, cols at colOff, ld=ldDst
__global__ void split_hlh_off(const float* __restrict__ src,
                              __nv_bfloat16* __restrict__ dst,
                              int K, int N, int ldDst, int colOff) {
    int idx = blockIdx.x * blockDim.x + threadIdx.x;
    if (idx >= K * N) return;
    int k = idx / N, n = idx - k * N;
    float x = src[idx];
    __nv_bfloat16 h = __float2bfloat16(x);
    __nv_bfloat16 l = __float2bfloat16(x - __bfloat162float(h));
    long long col = colOff + n;
    dst[(long long)k * ldDst + col]          = h;
    dst[(long long)(K + k) * ldDst + col]    = l;
    dst[(long long)(2*K + k) * ldDst + col]  = h;
}
// XA [4096x128] -> XAs [4096x384]: cols 0-63 -> hhl at 0/64/128, 64-127 -> 192/256/320
__global__ void split_hhl2(const float* __restrict__ src,
                           __nv_bfloat16* __restrict__ dst) {
    int idx = blockIdx.x * blockDim.x + threadIdx.x;
    if (idx >= NTOK * 128) return;
    int m = idx >> 7, c = idx & 127;
    int grp = c >> 6, k = c & 63;
    float x = src[idx];
    __nv_bfloat16 h = __float2bfloat16(x);
    __nv_bfloat16 l = __float2bfloat16(x - __bfloat162float(h));
    long long base = (long long)m * 384 + grp * 192;
    dst[base + k] = h; dst[base + 64 + k] = h; dst[base + 128 + k] = l;
}

// --------------- double-buffered cp.async bf16 tensor-core GEMM ------------
// C[M,N] fp32 = A[M,K] @ B[K,N] with leading dims ldA/ldB/ldC; batched over
// blockIdx.z. causal: 0 none; 1 scores tile-skip; 2 PV interleaved K-limit.
template<int BM, int BN, int BK, int WM, int WN>
__global__ __launch_bounds__(WM*WN*32)
void mma_gemm(const __nv_bfloat16* __restrict__ A,
              const __nv_bfloat16* __restrict__ B,
              float* __restrict__ C, int M, int N, int K,
              int ldA, int ldB, int ldC,
              long long sA, long long sB, long long sC,
              int accumulate, int causal)
{
    constexpr int NTH = WM * WN * 32;
    constexpr int WTM = BM / WM, WTN = BN / WN;
    constexpr int MT = WTM / 16, NTt = WTN / 8;
    constexpr int AP = BK + 8, BP = BN + 8;
    extern __shared__ __align__(16) __nv_bfloat16 smem[];
    __nv_bfloat16* AsBase = smem;                    // 2 * BM * AP
    __nv_bfloat16* BsBase = smem + 2 * BM * AP;      // 2 * BK * BP

    const int m0 = blockIdx.y * BM, n0 = blockIdx.x * BN;
    if (causal == 1 && n0 > ((m0 + BM - 1) >> 2)) return;
    int kend = K;
    if (causal == 2) {
        int kl = 3 * (((m0 + BM - 1) >> 2) + 1);
        kl = (kl + BK - 1) / BK * BK;
        if (kl < kend) kend = kl;
    }
    const int KT = kend / BK;

    const long long z = blockIdx.z;
    A += z * sA; B += z * sB; C += z * sC;

    const int tid = threadIdx.x, lane = tid & 31;
    const int wid = tid >> 5;
    const int wm = wid / WN, wn = wid % WN;

    float acc[MT][NTt][4] = {};

    auto load_stage = [&](int kt, int st) {
        const int k0 = kt * BK;
        __nv_bfloat16* As = AsBase + st * BM * AP;
        __nv_bfloat16* Bs = BsBase + st * BK * BP;
        #pragma unroll
        for (int i = tid; i < BM * BK / 8; i += NTH) {
            int r = i / (BK / 8), c = (i % (BK / 8)) * 8;
            cp_async16(As + r * AP + c, &A[(long long)(m0 + r) * ldA + k0 + c]);
        }
        #pragma unroll
        for (int i = tid; i < BK * BN / 8; i += NTH) {
            int r = i / (BN / 8), c = (i % (BN / 8)) * 8;
            cp_async16(Bs + r * BP + c, &B[(long long)(k0 + r) * ldB + n0 + c]);
        }
        asm volatile("cp.async.commit_group;");
    };

    load_stage(0, 0);

    for (int kt = 0; kt < KT; kt++) {
        const int st = kt & 1;
        if (kt + 1 < KT) {
            load_stage(kt + 1, st ^ 1);
            asm volatile("cp.async.wait_group 1;");
        } else {
            asm volatile("cp.async.wait_group 0;");
        }
        __syncthreads();
        __nv_bfloat16* As = AsBase + st * BM * AP;
        __nv_bfloat16* Bs = BsBase + st * BK * BP;

        #pragma unroll
        for (int ks = 0; ks < BK / 16; ks++) {
            uint32_t a[MT][4], b[NTt][2];
            #pragma unroll
            for (int mt = 0; mt < MT; mt++) {
                uint32_t s = (uint32_t)__cvta_generic_to_shared(
                    As + (wm*WTM + mt*16 + (lane & 15)) * AP + ks*16 + ((lane >> 4) << 3));
                asm volatile("ldmatrix.sync.aligned.m8n8.x4.shared.b16 {%0,%1,%2,%3}, [%4];"
                    : "=r"(a[mt][0]), "=r"(a[mt][1]), "=r"(a[mt][2]), "=r"(a[mt][3])
                    : "r"(s));
            }
            #pragma unroll
            for (int np = 0; np < NTt / 2; np++) {
                uint32_t s = (uint32_t)__cvta_generic_to_shared(
                    Bs + (ks*16 + (lane & 15)) * BP + wn*WTN + np*16 + ((lane >> 4) << 3));
                asm volatile("ldmatrix.sync.aligned.m8n8.x4.trans.shared.b16 {%0,%1,%2,%3}, [%4];"
                    : "=r"(b[np*2][0]), "=r"(b[np*2][1]),
                      "=r"(b[np*2+1][0]), "=r"(b[np*2+1][1])
                    : "r"(s));
            }
            #pragma unroll
            for (int mt = 0; mt < MT; mt++)
                #pragma unroll
                for (int nt = 0; nt < NTt; nt++)
                    asm volatile(
                        "mma.sync.aligned.m16n8k16.row.col.f32.bf16.bf16.f32 "
                        "{%0,%1,%2,%3}, {%4,%5,%6,%7}, {%8,%9}, {%0,%1,%2,%3};"
                        : "+f"(acc[mt][nt][0]), "+f"(acc[mt][nt][1]),
                          "+f"(acc[mt][nt][2]), "+f"(acc[mt][nt][3])
                        : "r"(a[mt][0]), "r"(a[mt][1]), "r"(a[mt][2]), "r"(a[mt][3]),
                          "r"(b[nt][0]), "r"(b[nt][1]));
        }
        __syncthreads();
    }

    #pragma unroll
    for (int mt = 0; mt < MT; mt++) {
        int row = m0 + wm*WTM + mt*16 + (lane >> 2);
        #pragma unroll
        for (int nt = 0; nt < NTt; nt++) {
            int col = n0 + wn*WTN + nt*8 + ((lane & 3) << 1);
            float2* p0 = (float2*)&C[(long long)row * ldC + col];
            float2* p1 = (float2*)&C[(long long)(row + 8) * ldC + col];
            float2 v0 = make_float2(acc[mt][nt][0], acc[mt][nt][1]);
            float2 v1 = make_float2(acc[mt][nt][2], acc[mt][nt][3]);
            if (accumulate) {
                float2 o0 = *p0, o1 = *p1;
                v0.x += o0.x; v0.y += o0.y; v1.x += o1.x; v1.y += o1.y;
            }
            *p0 = v0; *p1 = v1;
        }
    }
}

// ----------------------------- rope cos/sin table --------------------------
__global__ void rope_table_kernel() {
    int s = blockIdx.x;
    int i = threadIdx.x;
    double invf = exp(-(double)i * (log(10000.0) / 32.0));
    double ang  = (double)s * invf;
    g_cs_tab[s*32 + i] = make_float2((float)cos(ang), (float)sin(ang));
}

// ------ RoPE + Hadamard phase; reads combined QKV; emits Qa split ----------
__global__ void rope_phase_kernel() {
    long long idx = (long long)blockIdx.x * blockDim.x + threadIdx.x;
    if (idx >= (long long)NTOK * HID) return;
    int d = (int)(idx & 63);
    int h = (int)((idx >> 6) & 15);
    int t = (int)(idx >> 10);
    int b = t >> 11;
    int s = t & (SEQ - 1);
    int step = s & 3;
    float sgn = hsign(step, d);

    long long qoff = (long long)t * 3072 + h * 64 + d;
    long long qpo  = (d < 32) ? qoff + 32 : qoff - 32;
    int i = d & 31;
    float2 cs = g_cs_tab[s*32 + i];

    float qv = g_QKV[qoff],        qp = g_QKV[qpo];
    float kv = g_QKV[qoff + 1024], kp = g_QKV[qpo + 1024];
    float vv = g_QKV[qoff + 2048];
    float qr = (d < 32) ? (qv*cs.x - qp*cs.y) : (qv*cs.x + qp*cs.y);
    float kr = (d < 32) ? (kv*cs.x - kp*cs.y) : (kv*cs.x + kp*cs.y);

    int bh = b*NH + h;
    long long hoff = (long long)(bh*SEQ + s) * HD + d;
    float qa = qr * sgn * 0.125f;
    g_Ks[hoff] = kr * sgn * 0.5f;
    g_Vs[hoff] = vv * sgn * 0.5f;

    __nv_bfloat16 qh = __float2bfloat16(qa);
    __nv_bfloat16 ql = __float2bfloat16(qa - __bfloat162float(qh));
    long long qbase = (long long)(bh*SEQ + s) * (3*HD) + d;
    g_Qas[qbase]        = qh;
    g_Qas[qbase + HD]   = qh;
    g_Qas[qbase + 2*HD] = ql;
}

// ---- full_K / full_V per slot; emits split B-operands for both GEMMs ------
__global__ void reduce_full_kernel() {
    int idx = blockIdx.x * blockDim.x + threadIdx.x;
    if (idx >= NBH*NS*HD) return;
    int d    = idx & 63;
    int slot = (idx >> 6) & (NS - 1);
    int bh   = idx >> 15;
    long long base = (long long)(bh*SEQ + slot*KF) * HD + d;
    float sk = 0.f, sv = 0.f;
    #pragma unroll
    for (int j = 0; j < KF; j++) { sk += g_Ks[base + j*HD]; sv += g_Vs[base + j*HD]; }
    g_fullV[idx] = sv;

    __nv_bfloat16 kh = __float2bfloat16(sk);
    __nv_bfloat16 kl = __float2bfloat16(sk - __bfloat162float(kh));
    long long ktb = ((long long)bh * (3*HD) + d) * NS + slot;
    g_KTs[ktb]                        = kh;
    g_KTs[ktb + (long long)HD * NS]   = kl;
    g_KTs[ktb + (long long)2*HD * NS] = kh;

    __nv_bfloat16 vh = __float2bfloat16(sv);
    __nv_bfloat16 vl = __float2bfloat16(sv - __bfloat162float(vh));
    long long fvb = ((long long)bh * (3*NS) + 3*slot) * HD + d;
    g_FVs[fvb]        = vh;
    g_FVs[fvb + HD]   = vl;
    g_FVs[fvb + 2*HD] = vh;
}

// --------- softmax per query (one warp); W split only up to tile limit -----
__global__ void softmax_kernel() {
    int warp = (blockIdx.x * blockDim.x + threadIdx.x) >> 5;
    int lane = threadIdx.x & 31;
    if (warp >= NBH*SEQ) return;
    int bh = warp / SEQ;
    int q  = warp - bh*SEQ;
    int slot = q >> 2, step = q & 3;

    const __nv_bfloat16* qrow = g_Qas + (long long)warp * (3*HD);
    float qa0 = __bfloat162float(qrow[lane])      + __bfloat162float(qrow[2*HD + lane]);
    float qa1 = __bfloat162float(qrow[32 + lane]) + __bfloat162float(qrow[2*HD + 32 + lane]);

    long long krow = (long long)(bh*SEQ + slot*KF) * HD;
    float pk0 = 0.f, pk1 = 0.f;
    for (int j = 0; j <= step; j++) {
        pk0 += g_Ks[krow + j*HD + lane];
        pk1 += g_Ks[krow + j*HD + lane + 32];
    }
    float cs = qa0*pk0 + qa1*pk1;
    #pragma unroll
    for (int o = 16; o; o >>= 1) cs += __shfl_xor_sync(0xFFFFFFFFu, cs, o);

    float* row = g_scores + (long long)bh*SEQ*NS + (long long)q*NS;

    float m = cs;
    for (int s = lane; s < slot; s += 32) m = fmaxf(m, row[s]);
    #pragma unroll
    for (int o = 16; o; o >>= 1) m = fmaxf(m, __shfl_xor_sync(0xFFFFFFFFu, m, o));

    float e_cs = expf(cs - m);
    float lsum = 0.f;
    for (int s = lane; s < slot; s += 32) {
        float e = expf(row[s] - m);
        row[s] = e;
        lsum += e;
    }
    #pragma unroll
    for (int o = 16; o; o >>= 1) lsum += __shfl_xor_sync(0xFFFFFFFFu, lsum, o);
    float inv = 1.0f / (lsum + e_cs);

    // PV tile for this query reads slots 0..smax_tile only (BK=32, 3*(smax+1) exact)
    int smax_tile = (q | 127) >> 2;
    __nv_bfloat16* wrow = g_Ws + (long long)warp * (3*NS);
    for (int s = lane; s <= smax_tile; s += 32) {
        float w;
        if (s < slot)       w = row[s] * inv;
        else if (s == slot) w = e_cs * inv;
        else                w = 0.0f;
        __nv_bfloat16 h = __float2bfloat16(w);
        __nv_bfloat16 l = __float2bfloat16(w - __bfloat162float(h));
        wrow[3*s]     = h;
        wrow[3*s + 1] = h;
        wrow[3*s + 2] = l;
    }
    if (lane == 0) g_wcurr[warp] = e_cs * inv;
}

// --- current-slot V correction + output phase + head-major -> token-major --
__global__ void fixup_kernel() {
    int bhq = blockIdx.x;
    int d = threadIdx.x;
    int bh = bhq >> 11;
    int q  = bhq & (SEQ - 1);
    int slot = q >> 2, step = q & 3;

    float out = g_Ohead[(long long)bhq * HD + d];
    long long vrow = (long long)(bh*SEQ + slot*KF) * HD + d;
    float pv = 0.f;
    for (int j = 0; j <= step; j++) pv += g_Vs[vrow + j*HD];
    float fv = g_fullV[((long long)bh*NS + slot) * HD + d];
    float wc = g_wcurr[bhq];
    float val = (out + wc * (pv - fv)) * hsign(step, d) * 2.0f;

    int b = bh >> 4, h = bh & 15;
    int t = b*SEQ + q;
    g_Otok[(long long)t*HID + h*HD + d] = val;
}

// --------------------------------- launcher --------------------------------
extern "C" void kernel_launch(void* const* d_in, const int* in_sizes, int n_in,
                              void* d_out, int out_size)
{
    (void)in_sizes; (void)n_in; (void)out_size;
    const float* X  = (const float*)d_in[0];
    const float* Wq = (const float*)d_in[1];
    const float* Wk = (const float*)d_in[2];
    const float* Wv = (const float*)d_in[3];
    const float* Wo = (const float*)d_in[4];
    const float* Aq = (const float*)d_in[5];
    const float* Bq = (const float*)d_in[6];
    const float* Av = (const float*)d_in[7];
    const float* Bv = (const float*)d_in[8];
    const float* Ao = (const float*)d_in[9];
    const float* Bo = (const float*)d_in[10];
    float* Y = (float*)d_out;

    float *pQKV, *pXA, *pFV, *pSc, *pOh, *pOt;
    __nv_bfloat16 *pXs, *pWqkv, *pWs, *pAB, *pBs, *pXAs, *pQas, *pKTs, *pFVs, *pWw;
    cudaGetSymbolAddress((void**)&pQKV, g_QKV);
    cudaGetSymbolAddress((void**)&pXA,  g_XA);
    cudaGetSymbolAddress((void**)&pFV,  g_fullV);
    cudaGetSymbolAddress((void**)&pSc,  g_scores);
    cudaGetSymbolAddress((void**)&pOh,  g_Ohead);
    cudaGetSymbolAddress((void**)&pOt,  g_Otok);
    cudaGetSymbolAddress((void**)&pXs,  g_Xs);
    cudaGetSymbolAddress((void**)&pWqkv, g_Wqkv);
    cudaGetSymbolAddress((void**)&pWs,  g_Wsplit);
    cudaGetSymbolAddress((void**)&pAB,  g_AB);
    cudaGetSymbolAddress((void**)&pBs,  g_Bsplit);
    cudaGetSymbolAddress((void**)&pXAs, g_XAsplit);
    cudaGetSymbolAddress((void**)&pQas, g_Qas);
    cudaGetSymbolAddress((void**)&pKTs, g_KTs);
    cudaGetSymbolAddress((void**)&pFVs, g_FVs);
    cudaGetSymbolAddress((void**)&pWw,  g_Ws);

    // dynamic smem sizes
    const int SM_BIG = 2*(128*(64+8) + 64*(128+8))*2;   // 71680 B  <128,128,64,2,4>
    const int SM_PV  = 2*(128*(32+8) + 32*(64+8))*2;    // 29696 B  <128,64,32,4,2>
    static int attr_done = 0;
    if (!attr_done) {
        cudaFuncSetAttribute(mma_gemm<128,128,64,2,4>,
                             cudaFuncAttributeMaxDynamicSharedMemorySize, SM_BIG);
        cudaFuncSetAttribute(mma_gemm<128,64,32,4,2>,
                             cudaFuncAttributeMaxDynamicSharedMemorySize, SM_PV);
        attr_done = 1;
    }

    const int SPLIT_T = 256;
    #define GRID1D(n) (((n) + SPLIT_T - 1) / SPLIT_T)

    // ---- split X; assemble combined QKV weights + LoRA-A ----
    split_hhl<<<GRID1D(NTOK*HID), SPLIT_T>>>(X, pXs, NTOK, HID);
    split_hlh_off<<<GRID1D(HID*HID), SPLIT_T>>>(Wq, pWqkv, HID, HID, 3*HID, 0);
    split_hlh_off<<<GRID1D(HID*HID), SPLIT_T>>>(Wk, pWqkv, HID, HID, 3*HID, HID);
    split_hlh_off<<<GRID1D(HID*HID), SPLIT_T>>>(Wv, pWqkv, HID, HID, 3*HID, 2*HID);
    split_hlh_off<<<GRID1D(HID*LR), SPLIT_T>>>(Aq, pAB, HID, LR, 128, 0);
    split_hlh_off<<<GRID1D(HID*LR), SPLIT_T>>>(Av, pAB, HID, LR, 128, LR);

    // ---- combined QKV projection: [4096x3072] = Xs @ Wqkv ----
    {
        dim3 grid(3*HID/128, NTOK/128);   // 24 x 32
        mma_gemm<128,128,64,2,4><<<grid, 256, SM_BIG>>>(
            pXs, pWqkv, pQKV, NTOK, 3*HID, 3*HID, 3*HID, 3*HID, 3*HID,
            0,0,0, 0, 0);
    }
    // ---- LoRA stage-1 (q|v combined, N=128) ----
    {
        dim3 grid(1, NTOK/128);
        mma_gemm<128,128,64,2,4><<<grid, 256, SM_BIG>>>(
            pXs, pAB, pXA, NTOK, 128, 3*HID, 3*HID, 128, 128,
            0,0,0, 0, 0);
    }
    split_hhl2<<<GRID1D(NTOK*128), SPLIT_T>>>(pXA, pXAs);
    // ---- LoRA stage-2 accumulate into QKV (Q cols, then V cols) ----
    split_hlh_off<<<GRID1D(LR*HID), SPLIT_T>>>(Bq, pBs, LR, HID, HID, 0);
    {
        dim3 grid(HID/128, NTOK/128);
        mma_gemm<128,128,64,2,4><<<grid, 256, SM_BIG>>>(
            pXAs, pBs, pQKV, NTOK, HID, 3*LR, 384, HID, 3*HID,
            0,0,0, 1, 0);
    }
    split_hlh_off<<<GRID1D(LR*HID), SPLIT_T>>>(Bv, pBs, LR, HID, HID, 0);
    {
        dim3 grid(HID/128, NTOK/128);
        mma_gemm<128,128,64,2,4><<<grid, 256, SM_BIG>>>(
            pXAs + 192, pBs, pQKV + 2*HID, NTOK, HID, 3*LR, 384, HID, 3*HID,
            0,0,0, 1, 0);
    }

    // ---- RoPE + phase (emits Qa split), slot reduction ----
    rope_table_kernel<<<SEQ, 32>>>();
    rope_phase_kernel<<<GRID1D(NTOK*HID), SPLIT_T>>>();
    reduce_full_kernel<<<GRID1D(NBH*NS*HD), SPLIT_T>>>();

    // ---- scores = Qa @ fullKT (batched, causal tile-skip) ----
    {
        dim3 grid(NS/128, SEQ/128, NBH);
        mma_gemm<128,128,64,2,4><<<grid, 256, SM_BIG>>>(
            pQas, pKTs, pSc, SEQ, NS, 3*HD, 3*HD, NS, NS,
            (long long)SEQ*3*HD, (long long)3*HD*NS, (long long)SEQ*NS,
            0, /*causal=*/1);
    }
    softmax_kernel<<<(NBH*SEQ*32)/256, 256>>>();

    // ---- Ohead = W @ fullV (batched, interleaved causal K-limit) ----
    {
        dim3 grid(1, SEQ/128, NBH);
        mma_gemm<128,64,32,4,2><<<grid, 256, SM_PV>>>(
            pWw, pFVs, pOh, SEQ, HD, 3*NS, 3*NS, HD, HD,
            (long long)SEQ*3*NS, (long long)3*NS*HD, (long long)SEQ*HD,
            0, /*causal=*/2);
    }
    fixup_kernel<<<NBH*SEQ, HD>>>();

    // ---- O projection + LoRA ----
    split_hhl<<<GRID1D(NTOK*HID), SPLIT_T>>>(pOt, pXs, NTOK, HID);
    split_hlh_off<<<GRID1D(HID*HID), SPLIT_T>>>(Wo, pWs, HID, HID, HID, 0);
    {
        dim3 grid(HID/128, NTOK/128);
        mma_gemm<128,128,64,2,4><<<grid, 256, SM_BIG>>>(
            pXs, pWs, Y, NTOK, HID, 3*HID, 3*HID, HID, HID,
            0,0,0, 0, 0);
    }
    split_hlh_off<<<GRID1D(HID*LR), SPLIT_T>>>(Ao, pAB, HID, LR, LR, 0);
    {
        dim3 grid(1, NTOK/128);   // N=64
        mma_gemm<128,64,32,4,2><<<grid, 256, SM_PV>>>(
            pXs, pAB, pXA, NTOK, LR, 3*HID, 3*HID, LR, LR,
            0,0,0, 0, 0);
    }
    split_hhl<<<GRID1D(NTOK*LR), SPLIT_T>>>(pXA, pXAs, NTOK, LR);
    split_hlh_off<<<GRID1D(LR*HID), SPLIT_T>>>(Bo, pBs, LR, HID, HID, 0);
    {
        dim3 grid(HID/128, NTOK/128);
        mma_gemm<128,128,64,2,4><<<grid, 256, SM_BIG>>>(
            pXAs, pBs, Y, NTOK, HID, 3*LR, 3*LR, HID, HID,
            0,0,0, 1, 0);
    }
    #undef GRID1D
}